// round 12
// baseline (speedup 1.0000x reference)
#include <cuda_runtime.h>
#include <cuda_bf16.h>

// Fixed problem shapes
#define B    8
#define T    16
#define C    64
#define H    56
#define W_   56
#define HW   (H * W_)          // 3136
#define HW4  (HW / 4)          // 784  (float4)
#define HW2  (HW / 2)          // 1568 (float2)
#define DIM  8
#define POOL 7
#define FEAT (DIM * DIM)       // 64
#define DH   64
#define BC   (B * C)           // 512
#define LN_EPS 1e-5f

#define THREADS 1024
#define STAGE_BYTES (T * HW * 4)   // 200704 B dynamic smem

typedef unsigned long long ull;

__device__ __forceinline__ ull ffma2(ull a, ull b, ull c)
{
    ull d;
    asm("fma.rn.f32x2 %0, %1, %2, %3;" : "=l"(d) : "l"(a), "l"(b), "l"(c));
    return d;
}

// ---------------------------------------------------------------------------
// Fused kernel: one CTA per (b,c), 1024 threads. Whole 196 KB x-slice staged
// in smem; x read from DRAM exactly once, out written exactly once.
// ---------------------------------------------------------------------------
__global__ __launch_bounds__(THREADS, 1)
void fused_kernel(const float* __restrict__ x,
                  const float* __restrict__ pos,
                  const float* __restrict__ Wqk,
                  const float* __restrict__ gamma,
                  const float* __restrict__ beta,
                  float* __restrict__ out)
{
    extern __shared__ float stage[];             // [T][HW] = 196 KB
    __shared__ float s[T][FEAT];                 // 4 KB
    __shared__ float qk[T][2 * DH];              // 8 KB
    __shared__ float mu[T], rs[T];
    __shared__ __align__(16) ull a2[T * T];      // packed {w,w}, 2 KB

    const int bc  = blockIdx.x;
    const int b   = bc >> 6;
    const int c   = bc & 63;
    const int tid = threadIdx.x;

    // ---------------- load slice into smem (x read ONCE) ----------------
    // Assign each thread a fixed t (tid>>6 maps 1024 threads to 16 t, 64
    // threads per t): p runs over HW4=784 in steps of 64 -> 12.25 iters,
    // all independent (high MLP), fully coalesced per warp.
    {
        const float4* xb  = reinterpret_cast<const float4*>(x);
        float4*       st4 = reinterpret_cast<float4*>(stage);
        const int t   = tid >> 6;                // 0..15
        const int lp  = tid & 63;                // 0..63
        const float4* src = xb + ((b * T + t) * C + c) * HW4;
        float4*       dst = st4 + t * HW4;
        #pragma unroll
        for (int p = 0; p < 768; p += 64)
            dst[p + lp] = __ldcs(&src[p + lp]);
        if (lp < 16) dst[768 + lp] = __ldcs(&src[768 + lp]);
    }
    __syncthreads();

    // ---------------- pooling: exactly 1 (t,cell) task per thread --------
    {
        const int t    = tid >> 6;
        const int cell = tid & 63;
        const int ci   = cell >> 3;
        const int cj   = cell & 7;
        const float* r0 = stage + t * HW + (ci * POOL) * W_ + cj * POOL;
        float sum = 0.f;
        #pragma unroll
        for (int r = 0; r < POOL; r++)
            #pragma unroll
            for (int col = 0; col < POOL; col++)
                sum += r0[r * W_ + col];
        s[t][cell] = sum * (1.f / (POOL * POOL)) + pos[bc * (T * FEAT) + tid];
    }
    __syncthreads();

    // ---------------- LayerNorm ----------------
    if (tid < T) {
        float m = 0.f, v = 0.f;
        #pragma unroll
        for (int f = 0; f < FEAT; f++) { float val = s[tid][f]; m += val; v += val * val; }
        m *= (1.f / FEAT);
        v = v * (1.f / FEAT) - m * m;
        mu[tid] = m;
        rs[tid] = rsqrtf(v + LN_EPS);
    }
    __syncthreads();
    {
        const int t = tid >> 6, f = tid & 63;
        s[t][f] = (s[t][f] - mu[t]) * rs[t] * gamma[f] + beta[f];
    }
    __syncthreads();

    // ---------------- qk = s @ Wqk : 2048 outputs, 2 per thread ----------
    #pragma unroll
    for (int i = tid; i < T * 2 * DH; i += THREADS) {
        const int t = i >> 7;
        const int o = i & 127;
        float acc = 0.f;
        #pragma unroll
        for (int f = 0; f < FEAT; f++) acc += s[t][f] * __ldg(&Wqk[f * (2 * DH) + o]);
        qk[t][o] = acc;
    }
    __syncthreads();

    // ---------------- dots + softmax -> packed a2 ----------------
    if (tid < T * T) {
        const int i = tid >> 4;
        const int j = tid & 15;
        float d = 0.f;
        #pragma unroll
        for (int k = 0; k < DH; k++) d += qk[i][k] * qk[j][DH + k];
        d *= 0.125f;                             // DH^-0.5

        float mx = d;
        #pragma unroll
        for (int m = 8; m; m >>= 1) mx = fmaxf(mx, __shfl_xor_sync(0xffffffffu, mx, m, 16));
        float e = __expf(d - mx);
        float ss = e;
        #pragma unroll
        for (int m = 8; m; m >>= 1) ss += __shfl_xor_sync(0xffffffffu, ss, m, 16);

        const float w = e / ss;
        ull wp;
        asm("mov.b64 %0, {%1, %1};" : "=l"(wp) : "f"(w));
        a2[i * T + j] = wp;                      // [i][j]
    }
    __syncthreads();

    // ------- out[t] = x[t] + sum_j a[t][j]*x[j], one float2 per thread -----
    const ull* st2 = reinterpret_cast<const ull*>(stage);   // [T][HW2]
    ull*       ob2 = reinterpret_cast<ull*>(out);
    const int base2 = (b * T * C + c) * HW2;
    const int tstr2 = C * HW2;

    for (int p2 = tid; p2 < HW2; p2 += THREADS) {
        // 16 x[j] packed float2 register-resident (32 regs)
        ull xv[T];
        #pragma unroll
        for (int j = 0; j < T; j++)
            xv[j] = st2[j * HW2 + p2];

        #pragma unroll
        for (int t = 0; t < T; t++) {
            ull acc = xv[t];                     // residual
            #pragma unroll
            for (int jc = 0; jc < T; jc += 2) {
                const ulonglong2 w =
                    *reinterpret_cast<const ulonglong2*>(&a2[t * T + jc]);
                acc = ffma2(w.x, xv[jc    ], acc);
                acc = ffma2(w.y, xv[jc + 1], acc);
            }
            __stcs(&ob2[base2 + t * tstr2 + p2], acc);
        }
    }
}

// ---------------------------------------------------------------------------
extern "C" void kernel_launch(void* const* d_in, const int* in_sizes, int n_in,
                              void* d_out, int out_size)
{
    const float* x     = (const float*)d_in[0];   // (8,16,64,56,56)
    const float* pos   = (const float*)d_in[1];   // (512,16,64)
    const float* Wqk   = (const float*)d_in[2];   // (64,128)
    const float* gamma = (const float*)d_in[3];   // (64,)
    const float* beta  = (const float*)d_in[4];   // (64,)
    float*       out   = (float*)d_out;

    cudaFuncSetAttribute(fused_kernel,
                         cudaFuncAttributeMaxDynamicSharedMemorySize,
                         STAGE_BYTES);

    fused_kernel<<<BC, THREADS, STAGE_BYTES>>>(x, pos, Wqk, gamma, beta, out);
}

// round 13
// speedup vs baseline: 1.1176x; 1.1176x over previous
#include <cuda_runtime.h>
#include <cuda_bf16.h>

// Fixed problem shapes
#define B    8
#define T    16
#define C    64
#define H    56
#define W_   56
#define HW   (H * W_)          // 3136
#define HW4  (HW / 4)          // 784 (float4)
#define DIM  8
#define POOL 7
#define FEAT (DIM * DIM)       // 64
#define DH   64
#define BC   (B * C)           // 512
#define LN_EPS 1e-5f

#define CHUNK_B 4              // 51.4 MB x-chunk, L2-resident between passes

typedef unsigned long long ull;

// Static device scratch (no allocations allowed)
__device__ float g_pool[BC * T * FEAT];   // 2 MB
__device__ ull   g_attn2[BC * T * T];     // packed {w,w}, 1 MB

__device__ __forceinline__ ull ffma2(ull a, ull b, ull c)
{
    ull d;
    asm("fma.rn.f32x2 %0, %1, %2, %3;" : "=l"(d) : "l"(a), "l"(b), "l"(c));
    return d;
}

union F4U { float4 f; ull u[2]; };

// ---------------------------------------------------------------------------
// K1: one CTA per (b,t,c) slice in chunk. Stage 12.5 KB smem, 7x7 mean-pool,
// compile-time reduce offsets. (measured 12.1 us per 4096-block chunk)
// ---------------------------------------------------------------------------
__global__ __launch_bounds__(256, 8)
void pool_kernel(const float* __restrict__ x, int slice0)
{
    const int slice = slice0 + blockIdx.x;   // ((b*T + t)*C + c)
    const int c = slice % C;
    const int t = (slice / C) % T;
    const int b = slice / (T * C);
    const int tid = threadIdx.x;

    __shared__ float stage[HW];

    const float4* xs = reinterpret_cast<const float4*>(x) + (long)slice * HW4;
    float4* st4 = reinterpret_cast<float4*>(stage);
    st4[tid]        = xs[tid];
    st4[tid + 256]  = xs[tid + 256];
    st4[tid + 512]  = xs[tid + 512];
    if (tid < 16) st4[tid + 768] = xs[tid + 768];
    __syncthreads();

    const int cell = tid >> 2;
    const int sub  = tid & 3;
    const int ci   = cell >> 3;
    const int cj   = cell & 7;

    const float* r0 = stage + (ci * POOL + sub) * W_ + cj * POOL;
    float sum = 0.f;
    #pragma unroll
    for (int jj = 0; jj < POOL; jj++) sum += r0[jj];
    if (sub < 3) {
        #pragma unroll
        for (int jj = 0; jj < POOL; jj++) sum += r0[4 * W_ + jj];
    }
    sum += __shfl_xor_sync(0xffffffffu, sum, 1);
    sum += __shfl_xor_sync(0xffffffffu, sum, 2);
    if (sub == 0)
        g_pool[((b * C + c) * T + t) * FEAT + cell] = sum * (1.f / (POOL * POOL));
}

// ---------------------------------------------------------------------------
// K2: one CTA per (b,c) in chunk. +pos, LN, QK, dots, softmax -> packed a2.
// ---------------------------------------------------------------------------
__global__ __launch_bounds__(256, 4)
void attn_kernel(const float* __restrict__ pos,
                 const float* __restrict__ Wqk,
                 const float* __restrict__ gamma,
                 const float* __restrict__ beta,
                 int bc0)
{
    const int bc  = bc0 + blockIdx.x;
    const int tid = threadIdx.x;

    __shared__ float s[T][FEAT];
    __shared__ float qk[T][2 * DH];
    __shared__ float mu[T], rs[T];

    {
        float* sf = &s[0][0];
        const float* gp = g_pool + bc * (T * FEAT);
        const float* pp = pos    + bc * (T * FEAT);
        for (int i = tid; i < T * FEAT; i += 256) sf[i] = gp[i] + pp[i];
    }
    __syncthreads();

    if (tid < T) {
        float m = 0.f, v = 0.f;
        #pragma unroll
        for (int f = 0; f < FEAT; f++) { float val = s[tid][f]; m += val; v += val * val; }
        m *= (1.f / FEAT);
        v = v * (1.f / FEAT) - m * m;
        mu[tid] = m;
        rs[tid] = rsqrtf(v + LN_EPS);
    }
    __syncthreads();
    {
        float* sf = &s[0][0];
        for (int i = tid; i < T * FEAT; i += 256) {
            int t = i >> 6, f = i & 63;
            sf[i] = (sf[i] - mu[t]) * rs[t] * gamma[f] + beta[f];
        }
    }
    __syncthreads();

    for (int i = tid; i < T * 2 * DH; i += 256) {
        const int t = i >> 7;
        const int o = i & 127;
        float acc = 0.f;
        #pragma unroll
        for (int f = 0; f < FEAT; f++) acc += s[t][f] * __ldg(&Wqk[f * (2 * DH) + o]);
        qk[t][o] = acc;
    }
    __syncthreads();

    {
        const int i = tid >> 4;
        const int j = tid & 15;
        float d = 0.f;
        #pragma unroll
        for (int k = 0; k < DH; k++) d += qk[i][k] * qk[j][DH + k];
        d *= 0.125f;

        float mx = d;
        #pragma unroll
        for (int m = 8; m; m >>= 1) mx = fmaxf(mx, __shfl_xor_sync(0xffffffffu, mx, m, 16));
        float e = __expf(d - mx);
        float ss = e;
        #pragma unroll
        for (int m = 8; m; m >>= 1) ss += __shfl_xor_sync(0xffffffffu, ss, m, 16);

        const float w = e / ss;
        ull wp;
        asm("mov.b64 %0, {%1, %1};" : "=l"(wp) : "f"(w));
        g_attn2[bc * (T * T) + i * T + j] = wp;   // [i][j]
    }
}

// ---------------------------------------------------------------------------
// K3: grid (7, CHUNK_B*C) x 128 threads. One float4 position per thread:
// 16 independent LDG.128 upfront (MLP=16, L2-hot from K1), then t-loop with
// packed-weight LDS.128 + FFMA2, streaming float4 stores. Regs capped at 85
// via launch_bounds(128,6) -> 6 CTAs = 24 warps/SM. tstride is compile-time
// so all 16 load/store addresses are base+immediate (no address regs).
// ---------------------------------------------------------------------------
__global__ __launch_bounds__(128, 6)
void out_kernel(const float* __restrict__ x, float* __restrict__ out, int bc0)
{
    const int bc  = bc0 + blockIdx.y;
    const int tid = threadIdx.x;

    __shared__ __align__(16) ull a2[T * T];   // 2 KB packed {w,w}
    #pragma unroll
    for (int i = tid; i < T * T; i += 128) a2[i] = g_attn2[bc * (T * T) + i];
    __syncthreads();

    const int p4 = blockIdx.x * 128 + tid;    // [0, 896), valid < 784
    if (p4 >= HW4) return;

    const int b = bc >> 6;
    const int c = bc & 63;

    const float4* xb = reinterpret_cast<const float4*>(x);
    float4*       ob = reinterpret_cast<float4*>(out);

    const int base4 = (b * T * C + c) * HW4 + p4;
    const int tstr4 = C * HW4;                // compile-time constant

    // 16 independent loads, all in flight together (L2-hot)
    ull xv[T][2];
    #pragma unroll
    for (int j = 0; j < T; j++) {
        F4U v; v.f = __ldg(&xb[base4 + j * tstr4]);
        xv[j][0] = v.u[0];
        xv[j][1] = v.u[1];
    }

    #pragma unroll
    for (int t = 0; t < T; t++) {
        ull acc0 = xv[t][0];                  // residual
        ull acc1 = xv[t][1];
        #pragma unroll
        for (int jc = 0; jc < T; jc += 2) {
            const ulonglong2 w =
                *reinterpret_cast<const ulonglong2*>(&a2[t * T + jc]);
            acc0 = ffma2(w.x, xv[jc    ][0], acc0);
            acc1 = ffma2(w.x, xv[jc    ][1], acc1);
            acc0 = ffma2(w.y, xv[jc + 1][0], acc0);
            acc1 = ffma2(w.y, xv[jc + 1][1], acc1);
        }
        F4U r; r.u[0] = acc0; r.u[1] = acc1;
        __stcs(&ob[base4 + t * tstr4], r.f);
    }
}

// ---------------------------------------------------------------------------
extern "C" void kernel_launch(void* const* d_in, const int* in_sizes, int n_in,
                              void* d_out, int out_size)
{
    const float* x     = (const float*)d_in[0];   // (8,16,64,56,56)
    const float* pos   = (const float*)d_in[1];   // (512,16,64)
    const float* Wqk   = (const float*)d_in[2];   // (64,128)
    const float* gamma = (const float*)d_in[3];   // (64,)
    const float* beta  = (const float*)d_in[4];   // (64,)
    float*       out   = (float*)d_out;

    // Chunked pipeline: 51.4 MB x-chunk stays L2-resident between its pool
    // pass and its output pass.
    for (int b0 = 0; b0 < B; b0 += CHUNK_B) {
        pool_kernel<<<CHUNK_B * T * C, 256>>>(x, b0 * T * C);
        attn_kernel<<<CHUNK_B * C, 256>>>(pos, Wqk, gamma, beta, b0 * C);
        out_kernel<<<dim3(7, CHUNK_B * C), 128>>>(x, out, b0 * C);
    }
}